// round 14
// baseline (speedup 1.0000x reference)
#include <cuda_runtime.h>
#include <cstdint>

#define N_MAX 50000
#define M_MAX 800000
#define D 128
#define SCAN_BS 512

// Scratch — __device__ globals only (no allocs allowed).
__device__ __align__(16) static float g_bufA[N_MAX * D];   // x after input GEMM
__device__ __align__(16) static float g_xn[N_MAX * D];     // normalized layer input
__device__ __align__(16) static float g_c[N_MAX * D];      // current normalized routing state
__device__ __align__(16) static float g_cnew[N_MAX * D];   // layer output (unnormalized)
__device__ static int g_src[M_MAX];
__device__ static int g_trg[M_MAX];
__device__ static int g_deg[N_MAX];
__device__ static int g_cnt[N_MAX];
__device__ static int g_rowptr[N_MAX + 1];
__device__ static int g_adj[M_MAX];          // incoming-edge src ids grouped by trg
// decoupled-lookback scan state (flags zeroed per call by norm_zero_kernel)
__device__ static int g_flag[128];           // 0=invalid 1=aggregate 2=inclusive
__device__ static int g_agg[128];
__device__ static int g_incl[128];

// -------------------------------------------- idx convert + degree histogram
// edge_index is int32 (established R1/R2: int64 interpretation faults; int32 passes).
__global__ void idx_hist_kernel(const int* __restrict__ ei,
                                int* __restrict__ src, int* __restrict__ trg,
                                int* __restrict__ deg, int m) {
    int i = blockIdx.x * blockDim.x + threadIdx.x;
    if (i >= m) return;
    int s = ei[i];
    int t = ei[m + i];
    src[i] = s;
    trg[i] = t;
    atomicAdd(&deg[t], 1);
}

// ---------------------- single-pass exclusive scan (decoupled lookback)
// deg[0..n) -> rowptr[0..n]; rowptr[n] = m. One block per SCAN_BS elements.
__global__ void scan_lookback_kernel(const int* __restrict__ deg,
                                     int* __restrict__ rowptr,
                                     int* __restrict__ flag,
                                     int* __restrict__ agg,
                                     int* __restrict__ incl,
                                     int n, int m) {
    __shared__ int sm[SCAN_BS];
    __shared__ int s_base;
    int t = threadIdx.x;
    int b = blockIdx.x;
    int i = b * SCAN_BS + t;
    int v = (i < n) ? deg[i] : 0;
    sm[t] = v;
    __syncthreads();
    for (int off = 1; off < SCAN_BS; off <<= 1) {
        int y = (t >= off) ? sm[t - off] : 0;
        __syncthreads();
        sm[t] += y;
        __syncthreads();
    }
    int total = sm[SCAN_BS - 1];

    if (t == 0) {
        if (b == 0) {
            incl[0] = total;
            __threadfence();
            atomicExch(&flag[0], 2);
            s_base = 0;
        } else {
            agg[b] = total;
            __threadfence();
            atomicExch(&flag[b], 1);
            // lookback
            int sum = 0;
            int pred = b - 1;
            while (true) {
                int f;
                do { f = atomicAdd(&flag[pred], 0); } while (f == 0);
                if (f == 2) { sum += *((volatile int*)&incl[pred]); break; }
                sum += *((volatile int*)&agg[pred]);
                pred--;
            }
            incl[b] = sum + total;
            __threadfence();
            atomicExch(&flag[b], 2);
            s_base = sum;
        }
    }
    __syncthreads();
    int base = s_base;
    if (i < n) rowptr[i] = base + sm[t] - v;   // exclusive
    if (i == n - 1) rowptr[n] = m;
}

__global__ void scatter_kernel(const int* __restrict__ src, const int* __restrict__ trg,
                               const int* __restrict__ rowptr, int* __restrict__ cnt,
                               int* __restrict__ adj, int m) {
    int i = blockIdx.x * blockDim.x + threadIdx.x;
    if (i >= m) return;
    int tg = trg[i];
    int pos = rowptr[tg] + atomicAdd(&cnt[tg], 1);
    adj[pos] = src[i];
}

// ---------------------------------------------------------------- GEMM + bias
#define BM 32
__global__ void gemm_bias_kernel(const float* __restrict__ A,
                                 const float* __restrict__ W,
                                 const float* __restrict__ b,
                                 float* __restrict__ C, int n) {
    __shared__ float As[BM * D];
    int j = threadIdx.x;
    int row0 = blockIdx.x * BM;
    int nvalid = n - row0; if (nvalid > BM) nvalid = BM;

    const float4* A4 = (const float4*)(A + (size_t)row0 * D);
    float4* As4 = (float4*)As;
    for (int i = threadIdx.x; i < nvalid * (D / 4); i += blockDim.x) As4[i] = A4[i];
    __syncthreads();

    float acc[BM];
#pragma unroll
    for (int r = 0; r < BM; r++) acc[r] = 0.f;
    for (int k = 0; k < D; k++) {
        float w = W[k * D + j];
#pragma unroll
        for (int r = 0; r < BM; r++) acc[r] = fmaf(As[r * D + k], w, acc[r]);
    }
    float bj = b[j];
    for (int r = 0; r < nvalid; r++) C[(size_t)(row0 + r) * D + j] = acc[r] + bj;
}

// ------------------------------- channel normalize (+ zero deg/cnt/flags)
// First `node_blocks` blocks do the proven warp-per-node normalize; extra
// blocks zero the CSR counters (replaces two cudaMemsetAsync launches).
__global__ void norm_zero_kernel(const float* __restrict__ in, float* __restrict__ out,
                                 int n, int node_blocks,
                                 int* __restrict__ deg, int* __restrict__ cnt,
                                 int* __restrict__ flag) {
    int extra = (int)blockIdx.x - node_blocks;
    if (extra >= 0) {
        int i = extra * 256 + threadIdx.x;
        if (i < n) { deg[i] = 0; cnt[i] = 0; }
        if (extra == 0 && threadIdx.x < 128) flag[threadIdx.x] = 0;
        return;
    }
    int gw = (blockIdx.x * blockDim.x + threadIdx.x) >> 5;
    if (gw >= n) return;
    int lane = threadIdx.x & 31;
    float4 v = *(const float4*)(in + (size_t)gw * D + lane * 4);
    float ss = v.x * v.x + v.y * v.y + v.z * v.z + v.w * v.w;
    ss += __shfl_xor_sync(0xffffffffu, ss, 1);
    ss += __shfl_xor_sync(0xffffffffu, ss, 2);
    ss += __shfl_xor_sync(0xffffffffu, ss, 4);
    float inv = 1.0f / fmaxf(sqrtf(ss), 1e-12f);
    *(float4*)(out + (size_t)gw * D + lane * 4) =
        make_float4(v.x * inv, v.y * inv, v.z * inv, v.w * inv);
}

// plain normalize (layer-2 boundary)
__global__ void norm_kernel(const float* __restrict__ in, float* __restrict__ out, int n) {
    int gw = (blockIdx.x * blockDim.x + threadIdx.x) >> 5;
    if (gw >= n) return;
    int lane = threadIdx.x & 31;
    float4 v = *(const float4*)(in + (size_t)gw * D + lane * 4);
    float ss = v.x * v.x + v.y * v.y + v.z * v.z + v.w * v.w;
    ss += __shfl_xor_sync(0xffffffffu, ss, 1);
    ss += __shfl_xor_sync(0xffffffffu, ss, 2);
    ss += __shfl_xor_sync(0xffffffffu, ss, 4);
    float inv = 1.0f / fmaxf(sqrtf(ss), 1e-12f);
    *(float4*)(out + (size_t)gw * D + lane * 4) =
        make_float4(v.x * inv, v.y * inv, v.z * inv, v.w * inv);
}

// ------------------------------------------- fused routing iteration (R9 body)
// warp per target node v; TWO edges per warp-iteration (16 lanes each).
template <bool DO_NORM>
__global__ void iter_kernel(const int* __restrict__ rowptr, const int* __restrict__ adj,
                            const float* __restrict__ xn, const float* __restrict__ c,
                            float* __restrict__ out, int n) {
    int v = (blockIdx.x * blockDim.x + threadIdx.x) >> 5;
    if (v >= n) return;
    int lane = threadIdx.x & 31;
    int half = lane >> 4;
    int q = lane & 3;
    int ch = (lane & 15) >> 2;
    int dbase = ch * 32 + q * 8;

    // s[a] = sum of c[v][4a..4a+3]; lane a holds sv. Redistribute 8 per lane.
    float4 cv = *(const float4*)(c + (size_t)v * D + lane * 4);
    float sv = cv.x + cv.y + cv.z + cv.w;
    float sr[8];
#pragma unroll
    for (int j = 0; j < 8; j++)
        sr[j] = __shfl_sync(0xffffffffu, sv, q * 8 + j);

    // residual into half 0 only (merge would double-count otherwise)
    float4 a0 = make_float4(0.f, 0.f, 0.f, 0.f);
    float4 a1 = make_float4(0.f, 0.f, 0.f, 0.f);
    if (half == 0) {
        a0 = *(const float4*)(xn + (size_t)v * D + dbase);
        a1 = *(const float4*)(xn + (size_t)v * D + dbase + 4);
    }

    int beg = rowptr[v], end = rowptr[v + 1];
    int nit = (end - beg + 1) >> 1;
    for (int j = 0; j < nit; j++) {
        int e = beg + 2 * j + half;
        bool valid = (e < end);
        int s = adj[valid ? e : beg];
        const float* zp = xn + (size_t)s * D + dbase;
        float4 z0 = *(const float4*)(zp);
        float4 z1 = *(const float4*)(zp + 4);

        float p = z0.x * sr[0] + z0.y * sr[1] + z0.z * sr[2] + z0.w * sr[3]
                + z1.x * sr[4] + z1.y * sr[5] + z1.z * sr[6] + z1.w * sr[7];
        p += __shfl_xor_sync(0xffffffffu, p, 1);
        p += __shfl_xor_sync(0xffffffffu, p, 2);       // p = logit for channel ch
        float mx = fmaxf(p, __shfl_xor_sync(0xffffffffu, p, 4));
        mx = fmaxf(mx, __shfl_xor_sync(0xffffffffu, mx, 8));
        float ex = __expf(p - mx);
        float den = ex + __shfl_xor_sync(0xffffffffu, ex, 4);
        den += __shfl_xor_sync(0xffffffffu, den, 8);
        float w = valid ? __fdividef(ex, den) : 0.f;

        a0.x = fmaf(w, z0.x, a0.x);
        a0.y = fmaf(w, z0.y, a0.y);
        a0.z = fmaf(w, z0.z, a0.z);
        a0.w = fmaf(w, z0.w, a0.w);
        a1.x = fmaf(w, z1.x, a1.x);
        a1.y = fmaf(w, z1.y, a1.y);
        a1.z = fmaf(w, z1.z, a1.z);
        a1.w = fmaf(w, z1.w, a1.w);
    }

    // merge halves
    a0.x += __shfl_xor_sync(0xffffffffu, a0.x, 16);
    a0.y += __shfl_xor_sync(0xffffffffu, a0.y, 16);
    a0.z += __shfl_xor_sync(0xffffffffu, a0.z, 16);
    a0.w += __shfl_xor_sync(0xffffffffu, a0.w, 16);
    a1.x += __shfl_xor_sync(0xffffffffu, a1.x, 16);
    a1.y += __shfl_xor_sync(0xffffffffu, a1.y, 16);
    a1.z += __shfl_xor_sync(0xffffffffu, a1.z, 16);
    a1.w += __shfl_xor_sync(0xffffffffu, a1.w, 16);

    if (DO_NORM) {
        float ss = a0.x * a0.x + a0.y * a0.y + a0.z * a0.z + a0.w * a0.w
                 + a1.x * a1.x + a1.y * a1.y + a1.z * a1.z + a1.w * a1.w;
        ss += __shfl_xor_sync(0xffffffffu, ss, 1);
        ss += __shfl_xor_sync(0xffffffffu, ss, 2);
        float inv = 1.0f / fmaxf(sqrtf(ss), 1e-12f);
        a0.x *= inv; a0.y *= inv; a0.z *= inv; a0.w *= inv;
        a1.x *= inv; a1.y *= inv; a1.z *= inv; a1.w *= inv;
    }

    if (half == 0) {
        *(float4*)(out + (size_t)v * D + dbase)     = a0;
        *(float4*)(out + (size_t)v * D + dbase + 4) = a1;
    }
}

// ---------------------------------------------------------------- launch
extern "C" void kernel_launch(void* const* d_in, const int* in_sizes, int n_in,
                              void* d_out, int out_size) {
    const float* feat  = (const float*)d_in[0];
    const int*   ei    = (const int*)d_in[1];
    const float* lin_w = (const float*)d_in[2];
    const float* lin_b = (const float*)d_in[3];
    const float* mlp_w = (const float*)d_in[4];
    const float* mlp_b = (const float*)d_in[5];

    int n = in_sizes[0] / D;
    int m = in_sizes[1] / 2;

    float *bufA, *xn, *c, *cnew;
    int *src, *trg, *deg, *cnt, *rowptr, *adj, *flag, *agg, *incl;
    cudaGetSymbolAddress((void**)&bufA,   g_bufA);
    cudaGetSymbolAddress((void**)&xn,     g_xn);
    cudaGetSymbolAddress((void**)&c,      g_c);
    cudaGetSymbolAddress((void**)&cnew,   g_cnew);
    cudaGetSymbolAddress((void**)&src,    g_src);
    cudaGetSymbolAddress((void**)&trg,    g_trg);
    cudaGetSymbolAddress((void**)&deg,    g_deg);
    cudaGetSymbolAddress((void**)&cnt,    g_cnt);
    cudaGetSymbolAddress((void**)&rowptr, g_rowptr);
    cudaGetSymbolAddress((void**)&adj,    g_adj);
    cudaGetSymbolAddress((void**)&flag,   g_flag);
    cudaGetSymbolAddress((void**)&agg,    g_agg);
    cudaGetSymbolAddress((void**)&incl,   g_incl);

    int node_blocks = (n * 32 + 255) / 256;  // warp per node
    int zero_blocks = (n + 255) / 256;
    int nb = (n + SCAN_BS - 1) / SCAN_BS;    // 98 blocks — all co-resident
    size_t nbytes = (size_t)n * D * sizeof(float);

    // (1) x = feat @ lin_w + lin_b
    gemm_bias_kernel<<<(n + BM - 1) / BM, 128>>>(feat, lin_w, lin_b, bufA, n);
    // (2) xn = normalize(x); extra blocks zero deg/cnt/flags
    norm_zero_kernel<<<node_blocks + zero_blocks, 256>>>(bufA, xn, n, node_blocks,
                                                         deg, cnt, flag);
    // (3) edge convert + degree histogram
    idx_hist_kernel<<<(m + 255) / 256, 256>>>(ei, src, trg, deg, m);
    // (4) single-pass scan -> rowptr
    scan_lookback_kernel<<<nb, SCAN_BS>>>(deg, rowptr, flag, agg, incl, n, m);
    // (5) CSR scatter
    scatter_kernel<<<(m + 255) / 256, 256>>>(src, trg, rowptr, cnt, adj, m);

    // (6..8) layer 1 routing  — launch #6 = iter#1 (ncu -s 5 -c 1 lands here)
    iter_kernel<true ><<<node_blocks, 256>>>(rowptr, adj, xn, xn, c, n);
    iter_kernel<true ><<<node_blocks, 256>>>(rowptr, adj, xn, c, c, n);
    iter_kernel<false><<<node_blocks, 256>>>(rowptr, adj, xn, c, cnew, n);
    // (9) re-normalize for layer 2
    norm_kernel<<<node_blocks, 256>>>(cnew, xn, n);
    // (10..12) layer 2 routing
    iter_kernel<true ><<<node_blocks, 256>>>(rowptr, adj, xn, xn, c, n);
    iter_kernel<true ><<<node_blocks, 256>>>(rowptr, adj, xn, c, c, n);
    iter_kernel<false><<<node_blocks, 256>>>(rowptr, adj, xn, c, cnew, n);

    // out = x @ mlp_w + mlp_b
    gemm_bias_kernel<<<(n + BM - 1) / BM, 128>>>(cnew, mlp_w, mlp_b, (float*)d_out, n);
    // second tuple element: x
    if (out_size >= 2 * n * D)
        cudaMemcpyAsync((float*)d_out + (size_t)n * D, cnew, nbytes,
                        cudaMemcpyDeviceToDevice, 0);
}

// round 15
// speedup vs baseline: 1.0448x; 1.0448x over previous
#include <cuda_runtime.h>
#include <cuda_fp16.h>
#include <cstdint>

#define N_MAX 50000
#define M_MAX 800000
#define D 128
#define SCAN_BS 512

// Scratch — __device__ globals only (no allocs allowed).
__device__ __align__(16) static float   g_bufA[N_MAX * D];   // x after input GEMM
__device__ __align__(16) static float   g_xn[N_MAX * D];     // normalized layer input (fp32)
__device__ __align__(16) static __half2 g_xnh[N_MAX * D / 2];// fp16 mirror of xn (z gathers)
__device__ __align__(16) static float   g_c[N_MAX * D];      // current normalized routing state
__device__ __align__(16) static float   g_cnew[N_MAX * D];   // layer output (unnormalized)
__device__ static int g_src[M_MAX];
__device__ static int g_trg[M_MAX];
__device__ static int g_deg[N_MAX];
__device__ static int g_cnt[N_MAX];
__device__ static int g_tmp[N_MAX];          // block-local exclusive scan
__device__ static int g_bsum[256];           // per-block sums
__device__ static int g_rowptr[N_MAX + 1];
__device__ static int g_adj[M_MAX];          // incoming-edge src ids grouped by trg

// -------------------------------------------- idx convert + degree histogram
// edge_index is int32 (established R1/R2: int64 interpretation faults; int32 passes).
__global__ void idx_hist_kernel(const int* __restrict__ ei,
                                int* __restrict__ src, int* __restrict__ trg,
                                int* __restrict__ deg, int m) {
    int i = blockIdx.x * blockDim.x + threadIdx.x;
    if (i >= m) return;
    int s = ei[i];
    int t = ei[m + i];
    src[i] = s;
    trg[i] = t;
    atomicAdd(&deg[t], 1);
}

// Phase 1: per-block exclusive scan (Hillis-Steele) + block sum.
__global__ void scan_block_kernel(const int* __restrict__ deg, int* __restrict__ tmp,
                                  int* __restrict__ bsum, int n) {
    __shared__ int sm[SCAN_BS];
    int t = threadIdx.x;
    int i = blockIdx.x * SCAN_BS + t;
    int v = (i < n) ? deg[i] : 0;
    sm[t] = v;
    __syncthreads();
    for (int off = 1; off < SCAN_BS; off <<= 1) {
        int y = (t >= off) ? sm[t - off] : 0;
        __syncthreads();
        sm[t] += y;
        __syncthreads();
    }
    if (i < n) tmp[i] = sm[t] - v;              // exclusive
    if (t == SCAN_BS - 1) bsum[blockIdx.x] = sm[t];
}

// Phase 2: exclusive scan of block sums (nb <= 256), single block.
__global__ void scan_bsum_kernel(int* __restrict__ bsum, int nb) {
    __shared__ int sm[256];
    int t = threadIdx.x;
    int v = (t < nb) ? bsum[t] : 0;
    sm[t] = v;
    __syncthreads();
    for (int off = 1; off < 256; off <<= 1) {
        int y = (t >= off) ? sm[t - off] : 0;
        __syncthreads();
        sm[t] += y;
        __syncthreads();
    }
    if (t < nb) bsum[t] = sm[t] - v;            // exclusive
}

// Phase 3: rowptr[i] = tmp[i] + bsum[i/SCAN_BS]; rowptr[n] = m.
__global__ void scan_add_kernel(const int* __restrict__ tmp, const int* __restrict__ bsum,
                                int* __restrict__ rowptr, int n, int m) {
    int i = blockIdx.x * blockDim.x + threadIdx.x;
    if (i < n) rowptr[i] = tmp[i] + bsum[i / SCAN_BS];
    if (i == 0) rowptr[n] = m;
}

__global__ void scatter_kernel(const int* __restrict__ src, const int* __restrict__ trg,
                               const int* __restrict__ rowptr, int* __restrict__ cnt,
                               int* __restrict__ adj, int m) {
    int i = blockIdx.x * blockDim.x + threadIdx.x;
    if (i >= m) return;
    int tg = trg[i];
    int pos = rowptr[tg] + atomicAdd(&cnt[tg], 1);
    adj[pos] = src[i];
}

// ---------------------------------------------------------------- GEMM + bias
#define BM 32
__global__ void gemm_bias_kernel(const float* __restrict__ A,
                                 const float* __restrict__ W,
                                 const float* __restrict__ b,
                                 float* __restrict__ C, int n) {
    __shared__ float As[BM * D];
    int j = threadIdx.x;
    int row0 = blockIdx.x * BM;
    int nvalid = n - row0; if (nvalid > BM) nvalid = BM;

    const float4* A4 = (const float4*)(A + (size_t)row0 * D);
    float4* As4 = (float4*)As;
    for (int i = threadIdx.x; i < nvalid * (D / 4); i += blockDim.x) As4[i] = A4[i];
    __syncthreads();

    float acc[BM];
#pragma unroll
    for (int r = 0; r < BM; r++) acc[r] = 0.f;
    for (int k = 0; k < D; k++) {
        float w = W[k * D + j];
#pragma unroll
        for (int r = 0; r < BM; r++) acc[r] = fmaf(As[r * D + k], w, acc[r]);
    }
    float bj = b[j];
    for (int r = 0; r < nvalid; r++) C[(size_t)(row0 + r) * D + j] = acc[r] + bj;
}

// ------------------------- channel normalize -> fp32 out + fp16 mirror
__global__ void norm_kernel(const float* __restrict__ in, float* __restrict__ out,
                            __half2* __restrict__ outh, int n) {
    int gw = (blockIdx.x * blockDim.x + threadIdx.x) >> 5;
    if (gw >= n) return;
    int lane = threadIdx.x & 31;
    float4 v = *(const float4*)(in + (size_t)gw * D + lane * 4);
    float ss = v.x * v.x + v.y * v.y + v.z * v.z + v.w * v.w;
    ss += __shfl_xor_sync(0xffffffffu, ss, 1);
    ss += __shfl_xor_sync(0xffffffffu, ss, 2);
    ss += __shfl_xor_sync(0xffffffffu, ss, 4);
    float inv = 1.0f / fmaxf(sqrtf(ss), 1e-12f);
    float4 o = make_float4(v.x * inv, v.y * inv, v.z * inv, v.w * inv);
    *(float4*)(out + (size_t)gw * D + lane * 4) = o;
    __half2 h0 = __floats2half2_rn(o.x, o.y);
    __half2 h1 = __floats2half2_rn(o.z, o.w);
    uint2 hh = make_uint2(*(unsigned*)&h0, *(unsigned*)&h1);
    *(uint2*)(outh + (size_t)gw * (D / 2) + lane * 2) = hh;
}

// ------------------------------------------- fused routing iteration
// warp per target node v; TWO edges per warp-iteration (16 lanes each).
// z gathered from the fp16 mirror (256B/edge instead of 512B); all math fp32.
template <bool DO_NORM>
__global__ void iter_kernel(const int* __restrict__ rowptr, const int* __restrict__ adj,
                            const float* __restrict__ xn, const __half2* __restrict__ xnh,
                            const float* __restrict__ c,
                            float* __restrict__ out, int n) {
    int v = (blockIdx.x * blockDim.x + threadIdx.x) >> 5;
    if (v >= n) return;
    int lane = threadIdx.x & 31;
    int half = lane >> 4;
    int q = lane & 3;
    int ch = (lane & 15) >> 2;
    int dbase = ch * 32 + q * 8;

    // s[a] = sum of c[v][4a..4a+3]; lane a holds sv. Redistribute 8 per lane.
    float4 cv = *(const float4*)(c + (size_t)v * D + lane * 4);
    float sv = cv.x + cv.y + cv.z + cv.w;
    float sr[8];
#pragma unroll
    for (int j = 0; j < 8; j++)
        sr[j] = __shfl_sync(0xffffffffu, sv, q * 8 + j);

    // residual into half 0 only (merge would double-count otherwise)
    float4 a0 = make_float4(0.f, 0.f, 0.f, 0.f);
    float4 a1 = make_float4(0.f, 0.f, 0.f, 0.f);
    if (half == 0) {
        a0 = *(const float4*)(xn + (size_t)v * D + dbase);
        a1 = *(const float4*)(xn + (size_t)v * D + dbase + 4);
    }

    int beg = rowptr[v], end = rowptr[v + 1];
    int nit = (end - beg + 1) >> 1;
    for (int j = 0; j < nit; j++) {
        int e = beg + 2 * j + half;
        bool valid = (e < end);
        int s = adj[valid ? e : beg];
        // 8 halves = 16B = one LDG.128 per lane
        uint4 raw = *(const uint4*)(xnh + (size_t)s * (D / 2) + dbase / 2);
        float2 f0 = __half22float2(*(__half2*)&raw.x);
        float2 f1 = __half22float2(*(__half2*)&raw.y);
        float2 f2 = __half22float2(*(__half2*)&raw.z);
        float2 f3 = __half22float2(*(__half2*)&raw.w);
        float4 z0 = make_float4(f0.x, f0.y, f1.x, f1.y);
        float4 z1 = make_float4(f2.x, f2.y, f3.x, f3.y);

        float p = z0.x * sr[0] + z0.y * sr[1] + z0.z * sr[2] + z0.w * sr[3]
                + z1.x * sr[4] + z1.y * sr[5] + z1.z * sr[6] + z1.w * sr[7];
        p += __shfl_xor_sync(0xffffffffu, p, 1);
        p += __shfl_xor_sync(0xffffffffu, p, 2);       // p = logit for channel ch
        float mx = fmaxf(p, __shfl_xor_sync(0xffffffffu, p, 4));
        mx = fmaxf(mx, __shfl_xor_sync(0xffffffffu, mx, 8));
        float ex = __expf(p - mx);
        float den = ex + __shfl_xor_sync(0xffffffffu, ex, 4);
        den += __shfl_xor_sync(0xffffffffu, den, 8);
        float w = valid ? __fdividef(ex, den) : 0.f;

        a0.x = fmaf(w, z0.x, a0.x);
        a0.y = fmaf(w, z0.y, a0.y);
        a0.z = fmaf(w, z0.z, a0.z);
        a0.w = fmaf(w, z0.w, a0.w);
        a1.x = fmaf(w, z1.x, a1.x);
        a1.y = fmaf(w, z1.y, a1.y);
        a1.z = fmaf(w, z1.z, a1.z);
        a1.w = fmaf(w, z1.w, a1.w);
    }

    // merge halves
    a0.x += __shfl_xor_sync(0xffffffffu, a0.x, 16);
    a0.y += __shfl_xor_sync(0xffffffffu, a0.y, 16);
    a0.z += __shfl_xor_sync(0xffffffffu, a0.z, 16);
    a0.w += __shfl_xor_sync(0xffffffffu, a0.w, 16);
    a1.x += __shfl_xor_sync(0xffffffffu, a1.x, 16);
    a1.y += __shfl_xor_sync(0xffffffffu, a1.y, 16);
    a1.z += __shfl_xor_sync(0xffffffffu, a1.z, 16);
    a1.w += __shfl_xor_sync(0xffffffffu, a1.w, 16);

    if (DO_NORM) {
        float ss = a0.x * a0.x + a0.y * a0.y + a0.z * a0.z + a0.w * a0.w
                 + a1.x * a1.x + a1.y * a1.y + a1.z * a1.z + a1.w * a1.w;
        ss += __shfl_xor_sync(0xffffffffu, ss, 1);
        ss += __shfl_xor_sync(0xffffffffu, ss, 2);
        float inv = 1.0f / fmaxf(sqrtf(ss), 1e-12f);
        a0.x *= inv; a0.y *= inv; a0.z *= inv; a0.w *= inv;
        a1.x *= inv; a1.y *= inv; a1.z *= inv; a1.w *= inv;
    }

    if (half == 0) {
        *(float4*)(out + (size_t)v * D + dbase)     = a0;
        *(float4*)(out + (size_t)v * D + dbase + 4) = a1;
    }
}

// ---------------------------------------------------------------- launch
extern "C" void kernel_launch(void* const* d_in, const int* in_sizes, int n_in,
                              void* d_out, int out_size) {
    const float* feat  = (const float*)d_in[0];
    const int*   ei    = (const int*)d_in[1];
    const float* lin_w = (const float*)d_in[2];
    const float* lin_b = (const float*)d_in[3];
    const float* mlp_w = (const float*)d_in[4];
    const float* mlp_b = (const float*)d_in[5];

    int n = in_sizes[0] / D;
    int m = in_sizes[1] / 2;

    float *bufA, *xn, *c, *cnew;
    __half2* xnh;
    int *src, *trg, *deg, *cnt, *tmp, *bsum, *rowptr, *adj;
    cudaGetSymbolAddress((void**)&bufA,   g_bufA);
    cudaGetSymbolAddress((void**)&xn,     g_xn);
    cudaGetSymbolAddress((void**)&xnh,    g_xnh);
    cudaGetSymbolAddress((void**)&c,      g_c);
    cudaGetSymbolAddress((void**)&cnew,   g_cnew);
    cudaGetSymbolAddress((void**)&src,    g_src);
    cudaGetSymbolAddress((void**)&trg,    g_trg);
    cudaGetSymbolAddress((void**)&deg,    g_deg);
    cudaGetSymbolAddress((void**)&cnt,    g_cnt);
    cudaGetSymbolAddress((void**)&tmp,    g_tmp);
    cudaGetSymbolAddress((void**)&bsum,   g_bsum);
    cudaGetSymbolAddress((void**)&rowptr, g_rowptr);
    cudaGetSymbolAddress((void**)&adj,    g_adj);

    // ---- edge preprocessing + CSR build (once per call)  [R13-proven]
    cudaMemsetAsync(deg, 0, (size_t)n * sizeof(int), 0);
    cudaMemsetAsync(cnt, 0, (size_t)n * sizeof(int), 0);
    idx_hist_kernel<<<(m + 255) / 256, 256>>>(ei, src, trg, deg, m);
    int nb = (n + SCAN_BS - 1) / SCAN_BS;
    scan_block_kernel<<<nb, SCAN_BS>>>(deg, tmp, bsum, n);
    scan_bsum_kernel<<<1, 256>>>(bsum, nb);
    scan_add_kernel<<<(n + 255) / 256, 256>>>(tmp, bsum, rowptr, n, m);
    scatter_kernel<<<(m + 255) / 256, 256>>>(src, trg, rowptr, cnt, adj, m);

    // ---- x = feat @ lin_w + lin_b
    gemm_bias_kernel<<<(n + BM - 1) / BM, 128>>>(feat, lin_w, lin_b, bufA, n);

    int node_blocks = (n * 32 + 255) / 256;  // warp per node
    size_t nbytes = (size_t)n * D * sizeof(float);

    const float* x_in = bufA;
    for (int layer = 0; layer < 2; layer++) {
        norm_kernel<<<node_blocks, 256>>>(x_in, xn, xnh, n);
        iter_kernel<true ><<<node_blocks, 256>>>(rowptr, adj, xn, xnh, xn, c, n);   // t=0 (c==xn)
        iter_kernel<true ><<<node_blocks, 256>>>(rowptr, adj, xn, xnh, c, c, n);    // t=1
        iter_kernel<false><<<node_blocks, 256>>>(rowptr, adj, xn, xnh, c, cnew, n); // t=2 raw
        x_in = cnew;
    }

    // out = x @ mlp_w + mlp_b
    gemm_bias_kernel<<<(n + BM - 1) / BM, 128>>>(cnew, mlp_w, mlp_b, (float*)d_out, n);
    // second tuple element: x
    if (out_size >= 2 * n * D)
        cudaMemcpyAsync((float*)d_out + (size_t)n * D, cnew, nbytes,
                        cudaMemcpyDeviceToDevice, 0);
}